// round 1
// baseline (speedup 1.0000x reference)
#include <cuda_runtime.h>

// MultiScaleProcessor: input [64,256,256,3] f32 -> output [64,4,256,256,3] f32
// scales (sorted) = {32,64,128,256}; each resized bilinearly (linspace endpoints)
// then zero-padded symmetrically to 256x256.

#define HH 256
#define WW 256
#define NB 64
#define ROWF (WW * 3)      // 768 floats per row
#define ROWV (ROWF / 4)    // 192 float4 per row

__global__ __launch_bounds__(256) void msp_kernel(const float* __restrict__ in,
                                                  float* __restrict__ out) {
    const int y   = blockIdx.x;   // 0..255 output row
    const int sc  = blockIdx.y;   // 0..3 scale index (32<<sc)
    const int b   = blockIdx.z;   // 0..63 batch
    const int s   = 32 << sc;
    const int p   = (256 - s) >> 1;
    const int tid = threadIdx.x;

    float4* __restrict__ orow =
        (float4*)(out + ((((size_t)b * 4 + sc) * HH + y) * ROWF));

    if (s == 256) {
        // native resolution: straight row copy, 128-bit
        const float4* __restrict__ irow =
            (const float4*)(in + ((size_t)b * HH + y) * ROWF);
        if (tid < ROWV) orow[tid] = irow[tid];
        return;
    }

    if (y < p || y >= p + s) {
        // fully padded row: zero fill, 128-bit
        if (tid < ROWV) orow[tid] = make_float4(0.f, 0.f, 0.f, 0.f);
        return;
    }

    // compute row: bilinear into shared, then vectorized flush
    __shared__ __align__(16) float row[ROWF];

    const float inv = 255.0f / (float)(s - 1);
    const int   syi = y - p;
    const float fy  = (float)syi * inv;
    const int   y0  = (int)floorf(fy);
    const int   y1  = min(y0 + 1, HH - 1);
    const float wy  = fy - (float)y0;

    {
        const int x = tid;  // one output pixel per thread
        if (x < p || x >= p + s) {
            row[3 * x + 0] = 0.f;
            row[3 * x + 1] = 0.f;
            row[3 * x + 2] = 0.f;
        } else {
            const float fx = (float)(x - p) * inv;
            const int   x0 = (int)floorf(fx);
            const int   x1 = min(x0 + 1, WW - 1);
            const float wx = fx - (float)x0;

            const float* __restrict__ base = in + (size_t)b * (HH * ROWF);
            const float* __restrict__ r0   = base + (size_t)y0 * ROWF;
            const float* __restrict__ r1   = base + (size_t)y1 * ROWF;

            const float wx0 = 1.f - wx;
            const float wy0 = 1.f - wy;
#pragma unroll
            for (int c = 0; c < 3; c++) {
                const float t = __ldg(r0 + 3 * x0 + c) * wx0 +
                                __ldg(r0 + 3 * x1 + c) * wx;
                const float bm = __ldg(r1 + 3 * x0 + c) * wx0 +
                                 __ldg(r1 + 3 * x1 + c) * wx;
                row[3 * x + c] = t * wy0 + bm * wy;
            }
        }
    }
    __syncthreads();
    if (tid < ROWV) orow[tid] = ((const float4*)row)[tid];
}

extern "C" void kernel_launch(void* const* d_in, const int* in_sizes, int n_in,
                              void* d_out, int out_size) {
    const float* in  = (const float*)d_in[0];
    float*       out = (float*)d_out;
    (void)in_sizes; (void)n_in; (void)out_size;

    dim3 grid(HH, 4, NB);   // row x scale x batch
    msp_kernel<<<grid, 256>>>(in, out);
}